// round 6
// baseline (speedup 1.0000x reference)
#include <cuda_runtime.h>
#include <cuda_bf16.h>
#include <mma.h>

using namespace nvcuda;

#define MAXN     100000
#define MAXN_PAD 100224      // padded so full 128-row tiles can store unguarded
#define FIN  256
#define FOUT 64

// Scratch (device globals — allocation is forbidden)
__device__ float g_h[MAXN_PAD * FOUT];  // projected features (L2-resident)
__device__ float g_as[MAXN];            // h · att_src
__device__ float g_ad[MAXN];            // h · att_dst
__device__ float g_den[MAXN];           // Σ p over incoming real edges

static __device__ __forceinline__ float leaky(float v) {
    return v > 0.0f ? v : 0.2f * v;
}

static __device__ __forceinline__ float tf32_rna(float v) {
    unsigned u;
    asm("cvt.rna.tf32.f32 %0, %1;" : "=r"(u) : "f"(v));
    return __uint_as_float(u);
}

// ---------------------------------------------------------------------------
// K1: h = x @ W via split-TF32 tensor cores.
//     BM=128, BN=64, BK=16. 8 warps: 4 along M x 2 along N, each warp owns
//     a 32x32 output tile (2x2 of 16x16 wmma frags). v = hi + lo;
//     acc += hi*hi + hi*lo + lo*hi  (lo*lo dropped, ~2^-22).
// ---------------------------------------------------------------------------
#define LDA 20   // 16 + 4 pad
#define LDB 68   // 64 + 4 pad

__global__ __launch_bounds__(256) void k_gemm_tc(const float* __restrict__ x,
                                                 const float* __restrict__ W,
                                                 int n) {
    __shared__ float As_hi[128][LDA];
    __shared__ float As_lo[128][LDA];
    __shared__ float Bs_hi[16][LDB];
    __shared__ float Bs_lo[16][LDB];

    const int tid  = threadIdx.x;
    const int row0 = blockIdx.x * 128;
    const int w    = tid >> 5;
    const int wm   = w & 3;          // 0..3 -> M offset wm*32
    const int wn   = w >> 2;         // 0..1 -> N offset wn*32

    wmma::fragment<wmma::accumulator, 16, 16, 8, float> acc[2][2];
#pragma unroll
    for (int i = 0; i < 2; i++)
#pragma unroll
        for (int j = 0; j < 2; j++) wmma::fill_fragment(acc[i][j], 0.0f);

    for (int k0 = 0; k0 < FIN; k0 += 16) {
        // Load A tile: 128 rows x 16 k = 512 float4, 2 per thread
#pragma unroll
        for (int l = 0; l < 2; l++) {
            int idx = tid + l * 256;          // 0..511
            int r = idx >> 2, q = idx & 3;
            float4 v = make_float4(0.f, 0.f, 0.f, 0.f);
            int gr = row0 + r;
            if (gr < n)
                v = *(const float4*)(x + (size_t)gr * FIN + k0 + q * 4);
            float h0 = tf32_rna(v.x), h1 = tf32_rna(v.y),
                  h2 = tf32_rna(v.z), h3 = tf32_rna(v.w);
            As_hi[r][q * 4 + 0] = h0; As_lo[r][q * 4 + 0] = tf32_rna(v.x - h0);
            As_hi[r][q * 4 + 1] = h1; As_lo[r][q * 4 + 1] = tf32_rna(v.y - h1);
            As_hi[r][q * 4 + 2] = h2; As_lo[r][q * 4 + 2] = tf32_rna(v.z - h2);
            As_hi[r][q * 4 + 3] = h3; As_lo[r][q * 4 + 3] = tf32_rna(v.w - h3);
        }
        // Load B tile: 16 k x 64 cols = 256 float4, 1 per thread
        {
            int k = tid >> 4, cq = tid & 15;
            float4 v = *(const float4*)(W + (size_t)(k0 + k) * FOUT + cq * 4);
            float h0 = tf32_rna(v.x), h1 = tf32_rna(v.y),
                  h2 = tf32_rna(v.z), h3 = tf32_rna(v.w);
            Bs_hi[k][cq * 4 + 0] = h0; Bs_lo[k][cq * 4 + 0] = tf32_rna(v.x - h0);
            Bs_hi[k][cq * 4 + 1] = h1; Bs_lo[k][cq * 4 + 1] = tf32_rna(v.y - h1);
            Bs_hi[k][cq * 4 + 2] = h2; Bs_lo[k][cq * 4 + 2] = tf32_rna(v.z - h2);
            Bs_hi[k][cq * 4 + 3] = h3; Bs_lo[k][cq * 4 + 3] = tf32_rna(v.w - h3);
        }
        __syncthreads();

#pragma unroll
        for (int kk = 0; kk < 16; kk += 8) {
            wmma::fragment<wmma::matrix_a, 16, 16, 8, wmma::precision::tf32,
                           wmma::row_major> a_hi[2], a_lo[2];
            wmma::fragment<wmma::matrix_b, 16, 16, 8, wmma::precision::tf32,
                           wmma::row_major> b_hi[2], b_lo[2];
#pragma unroll
            for (int i = 0; i < 2; i++) {
                wmma::load_matrix_sync(a_hi[i], &As_hi[wm * 32 + i * 16][kk], LDA);
                wmma::load_matrix_sync(a_lo[i], &As_lo[wm * 32 + i * 16][kk], LDA);
                wmma::load_matrix_sync(b_hi[i], &Bs_hi[kk][wn * 32 + i * 16], LDB);
                wmma::load_matrix_sync(b_lo[i], &Bs_lo[kk][wn * 32 + i * 16], LDB);
            }
#pragma unroll
            for (int i = 0; i < 2; i++)
#pragma unroll
                for (int j = 0; j < 2; j++) {
                    wmma::mma_sync(acc[i][j], a_hi[i], b_hi[j], acc[i][j]);
                    wmma::mma_sync(acc[i][j], a_hi[i], b_lo[j], acc[i][j]);
                    wmma::mma_sync(acc[i][j], a_lo[i], b_hi[j], acc[i][j]);
                }
        }
        __syncthreads();
    }

    // Store h (g_h is row-padded so full-tile stores are in-bounds)
#pragma unroll
    for (int i = 0; i < 2; i++)
#pragma unroll
        for (int j = 0; j < 2; j++) {
            int r = row0 + wm * 32 + i * 16;
            int c = wn * 32 + j * 16;
            wmma::store_matrix_sync(g_h + (size_t)r * FOUT + c, acc[i][j],
                                    FOUT, wmma::mem_row_major);
        }
}

// ---------------------------------------------------------------------------
// K2: per-node attention halves (one warp per node) + den init
// ---------------------------------------------------------------------------
__global__ __launch_bounds__(256) void k_attn(const float* __restrict__ att_src,
                                              const float* __restrict__ att_dst,
                                              int n) {
    int node = (blockIdx.x * blockDim.x + threadIdx.x) >> 5;
    int lane = threadIdx.x & 31;
    if (node >= n) return;
    const float* hr = g_h + (size_t)node * FOUT;
    float h0 = hr[lane], h1 = hr[lane + 32];
    float s = h0 * __ldg(att_src + lane) + h1 * __ldg(att_src + lane + 32);
    float d = h0 * __ldg(att_dst + lane) + h1 * __ldg(att_dst + lane + 32);
#pragma unroll
    for (int o = 16; o > 0; o >>= 1) {
        s += __shfl_xor_sync(0xFFFFFFFFu, s, o);
        d += __shfl_xor_sync(0xFFFFFFFFu, d, o);
    }
    if (lane == 0) {
        g_as[node]  = s;
        g_ad[node]  = d;
        g_den[node] = 0.0f;
    }
}

// ---------------------------------------------------------------------------
// K3: fused edge pass — 16 threads/edge, unnormalized p accumulate
// ---------------------------------------------------------------------------
__global__ __launch_bounds__(256) void k_edge(const int* __restrict__ ei,
                                              float* __restrict__ out, int e) {
    unsigned gid  = blockIdx.x * 256u + threadIdx.x;
    int edge = (int)(gid >> 4);
    if (edge >= e) return;
    int sub  = (int)(gid & 15);
    int lane = threadIdx.x & 31;

    int s = __ldg(ei + edge);
    int d = __ldg(ei + e + edge);

    float p = 0.0f;
    if (sub == 0)
        p = __expf(leaky(__ldg(&g_as[s]) + __ldg(&g_ad[d])));
    p = __shfl_sync(0xFFFFFFFFu, p, lane & 16);   // lane 0 / 16 broadcast
    if (sub == 0)
        atomicAdd(&g_den[d], p);                  // RED, no return

    const float4 hv = *(const float4*)(g_h + (size_t)s * FOUT + sub * 4);
    float* dst = out + (size_t)d * FOUT + sub * 4;
    asm volatile("red.global.add.v4.f32 [%0], {%1, %2, %3, %4};"
                 :: "l"(dst), "f"(p * hv.x), "f"(p * hv.y),
                    "f"(p * hv.z), "f"(p * hv.w)
                 : "memory");
}

// ---------------------------------------------------------------------------
// K4: finalize — add self-loop, normalize, add bias
// ---------------------------------------------------------------------------
__global__ __launch_bounds__(256) void k_fin(float* __restrict__ out,
                                             const float* __restrict__ bias,
                                             int n) {
    int idx = blockIdx.x * blockDim.x + threadIdx.x;
    if (idx >= n * FOUT) return;
    int i = idx >> 6, c = idx & 63;
    float p = __expf(leaky(g_as[i] + g_ad[i]));   // self-loop weight
    float inv = 1.0f / (g_den[i] + p + 1e-16f);
    out[idx] = (out[idx] + p * g_h[idx]) * inv + __ldg(bias + c);
}

// ---------------------------------------------------------------------------
extern "C" void kernel_launch(void* const* d_in, const int* in_sizes, int n_in,
                              void* d_out, int out_size) {
    const float* x       = (const float*)d_in[0];
    const int*   ei      = (const int*)d_in[1];
    const float* W       = (const float*)d_in[2];
    const float* att_src = (const float*)d_in[3];
    const float* att_dst = (const float*)d_in[4];
    const float* bias    = (const float*)d_in[5];
    float* out = (float*)d_out;

    const int n = in_sizes[0] / FIN;   // 100000
    const int e = in_sizes[1] / 2;     // 3200000

    cudaMemsetAsync(out, 0, (size_t)n * FOUT * sizeof(float));

    // K1: projection (split-TF32 tensor cores)
    k_gemm_tc<<<(n + 127) / 128, 256>>>(x, W, n);

    // K2: attention halves + den init
    k_attn<<<(n + 7) / 8, 256>>>(att_src, att_dst, n);

    // K3: fused edge pass
    {
        long long total = (long long)e * 16;
        int blocks = (int)((total + 255) / 256);
        k_edge<<<blocks, 256>>>(ei, out, e);
    }

    // K4: self-loop + normalize + bias
    k_fin<<<(n * FOUT + 255) / 256, 256>>>(out, bias, n);
}

// round 8
// speedup vs baseline: 1.6064x; 1.6064x over previous
#include <cuda_runtime.h>
#include <cuda_bf16.h>

#define MAXN 100000
#define MAXE 3200000
#define FIN  256
#define FOUT 64

// Scratch (device globals — allocation is forbidden)
__device__ float g_h[MAXN * FOUT];     // projected features (25.6 MB, L2-resident)
__device__ float g_as[MAXN];           // h · att_src
__device__ float g_ad[MAXN];           // h · att_dst
__device__ int   g_cnt[MAXN];          // in-degree (real edges)
__device__ int   g_offs[MAXN];         // CSR offsets (exclusive scan of cnt)
__device__ int   g_bsum[512];          // scan block sums
__device__ int   g_src[MAXE];          // dst-sorted source ids

static __device__ __forceinline__ float leaky(float v) {
    return v > 0.0f ? v : 0.2f * v;
}

// ---------------------------------------------------------------------------
// K1: h = x @ W  (scalar SGEMM, BM=128, BN=64, BK=16, 8x4/thread)
//     Fused epilogue: a_src, a_dst per row; cnt init = 0.
// ---------------------------------------------------------------------------
__global__ __launch_bounds__(256) void k_gemm(const float* __restrict__ x,
                                              const float* __restrict__ W,
                                              const float* __restrict__ att_src,
                                              const float* __restrict__ att_dst,
                                              int n) {
    __shared__ float  As[128][17];
    __shared__ float4 Bs[16][16];

    const int tid  = threadIdx.x;
    const int row0 = blockIdx.x * 128;
    const int tcol = tid & 15;
    const int trow = tid >> 4;

    float acc[8][4];
#pragma unroll
    for (int i = 0; i < 8; i++)
#pragma unroll
        for (int j = 0; j < 4; j++) acc[i][j] = 0.0f;

    for (int k0 = 0; k0 < FIN; k0 += 16) {
#pragma unroll
        for (int l = 0; l < 2; l++) {
            int idx = tid + l * 256;
            int r = idx >> 2, q = idx & 3;
            float4 v = make_float4(0.f, 0.f, 0.f, 0.f);
            int gr = row0 + r;
            if (gr < n)
                v = *(const float4*)(x + (size_t)gr * FIN + k0 + q * 4);
            As[r][q * 4 + 0] = v.x; As[r][q * 4 + 1] = v.y;
            As[r][q * 4 + 2] = v.z; As[r][q * 4 + 3] = v.w;
        }
        {
            int k = tid >> 4, cq = tid & 15;
            Bs[k][cq] = *(const float4*)(W + (size_t)(k0 + k) * FOUT + cq * 4);
        }
        __syncthreads();

#pragma unroll
        for (int kk = 0; kk < 16; kk++) {
            float4 b = Bs[kk][tcol];
#pragma unroll
            for (int i = 0; i < 8; i++) {
                float a = As[trow + 16 * i][kk];
                acc[i][0] += a * b.x;
                acc[i][1] += a * b.y;
                acc[i][2] += a * b.z;
                acc[i][3] += a * b.w;
            }
        }
        __syncthreads();
    }

    const float4 asv = *(const float4*)(att_src + tcol * 4);
    const float4 adv = *(const float4*)(att_dst + tcol * 4);

#pragma unroll
    for (int i = 0; i < 8; i++) {
        int r = row0 + trow + 16 * i;
        float sa = acc[i][0] * asv.x + acc[i][1] * asv.y
                 + acc[i][2] * asv.z + acc[i][3] * asv.w;
        float sd = acc[i][0] * adv.x + acc[i][1] * adv.y
                 + acc[i][2] * adv.z + acc[i][3] * adv.w;
#pragma unroll
        for (int o = 8; o > 0; o >>= 1) {
            sa += __shfl_xor_sync(0xFFFFFFFFu, sa, o);
            sd += __shfl_xor_sync(0xFFFFFFFFu, sd, o);
        }
        if (r < n) {
            *(float4*)(g_h + (size_t)r * FOUT + tcol * 4) =
                make_float4(acc[i][0], acc[i][1], acc[i][2], acc[i][3]);
            if (tcol == 0) {
                g_as[r]  = sa;
                g_ad[r]  = sd;
                g_cnt[r] = 0;
            }
        }
    }
}

// ---------------------------------------------------------------------------
// K2: in-degree histogram
// ---------------------------------------------------------------------------
__global__ __launch_bounds__(256) void k_hist(const int* __restrict__ ei, int e) {
    int i = blockIdx.x * 256 + threadIdx.x;
    if (i < e) atomicAdd(&g_cnt[__ldg(ei + e + i)], 1);
}

// ---------------------------------------------------------------------------
// K3a/b/c: exclusive prefix scan over cnt -> offs
// ---------------------------------------------------------------------------
__global__ __launch_bounds__(256) void k_scan1(int n) {
    __shared__ int sh[256];
    int i = blockIdx.x * 256 + threadIdx.x;
    int v = (i < n) ? g_cnt[i] : 0;
    sh[threadIdx.x] = v;
    __syncthreads();
#pragma unroll
    for (int o = 1; o < 256; o <<= 1) {
        int t = (threadIdx.x >= o) ? sh[threadIdx.x - o] : 0;
        __syncthreads();
        sh[threadIdx.x] += t;
        __syncthreads();
    }
    if (i < n) g_offs[i] = sh[threadIdx.x] - v;        // exclusive
    if (threadIdx.x == 255) g_bsum[blockIdx.x] = sh[255];
}

__global__ __launch_bounds__(512) void k_scan2(int nb) {
    __shared__ int sh[512];
    int t = threadIdx.x;
    int v = (t < nb) ? g_bsum[t] : 0;
    sh[t] = v;
    __syncthreads();
#pragma unroll
    for (int o = 1; o < 512; o <<= 1) {
        int u = (t >= o) ? sh[t - o] : 0;
        __syncthreads();
        sh[t] += u;
        __syncthreads();
    }
    if (t < nb) g_bsum[t] = sh[t] - v;                  // exclusive
}

__global__ __launch_bounds__(256) void k_scan3(int n) {
    int i = blockIdx.x * 256 + threadIdx.x;
    if (i < n) g_offs[i] += g_bsum[blockIdx.x];
}

// ---------------------------------------------------------------------------
// K4: scatter src ids into dst-sorted order.
//     Advances offs[d] to its end position; agg recovers start = end - cnt.
// ---------------------------------------------------------------------------
__global__ __launch_bounds__(256) void k_scatter(const int* __restrict__ ei, int e) {
    int i = blockIdx.x * 256 + threadIdx.x;
    if (i >= e) return;
    int s = __ldg(ei + i);
    int d = __ldg(ei + e + i);
    int pos = atomicAdd(&g_offs[d], 1);
    g_src[pos] = s;
}

// ---------------------------------------------------------------------------
// K5: warp-per-dst aggregation. Two 16-lane subgroups process 2 edges/iter,
//     accumulate p*h in registers, reduce den in-lane; epilogue folds
//     self-loop + normalization + bias; out written exactly once.
// ---------------------------------------------------------------------------
__global__ __launch_bounds__(256) void k_agg(const float* __restrict__ bias,
                                             float* __restrict__ out, int n) {
    int node = (int)((blockIdx.x * 256u + threadIdx.x) >> 5);
    if (node >= n) return;
    int lane = threadIdx.x & 31;
    int sub  = lane & 15;

    int end   = g_offs[node];            // post-scatter: end offset
    int start = end - g_cnt[node];
    float adi = g_ad[node];

    float4 acc = make_float4(0.f, 0.f, 0.f, 0.f);
    float denl = 0.0f;

    for (int base = start; base < end; base += 2) {
        int idx = base + (lane >> 4);
        bool valid = idx < end;
        int s = valid ? __ldg(&g_src[idx]) : 0;
        float p = 0.0f;
        if (sub == 0 && valid)
            p = __expf(leaky(__ldg(&g_as[s]) + adi));
        p = __shfl_sync(0xFFFFFFFFu, p, lane & 16);
        if (sub == 0) denl += p;
        if (valid) {
            const float4 hv = *(const float4*)(g_h + (size_t)s * FOUT + sub * 4);
            acc.x += p * hv.x;
            acc.y += p * hv.y;
            acc.z += p * hv.z;
            acc.w += p * hv.w;
        }
    }

    // combine the two subgroups
    acc.x += __shfl_xor_sync(0xFFFFFFFFu, acc.x, 16);
    acc.y += __shfl_xor_sync(0xFFFFFFFFu, acc.y, 16);
    acc.z += __shfl_xor_sync(0xFFFFFFFFu, acc.z, 16);
    acc.w += __shfl_xor_sync(0xFFFFFFFFu, acc.w, 16);
    float den = __shfl_sync(0xFFFFFFFFu, denl, 0)
              + __shfl_sync(0xFFFFFFFFu, denl, 16);

    float asi = g_as[node];
    float ps  = __expf(leaky(asi + adi));           // self-loop weight
    float inv = 1.0f / (den + ps + 1e-16f);

    if (lane < 16) {
        const float4 hi4 = *(const float4*)(g_h + (size_t)node * FOUT + sub * 4);
        const float4 b4  = *(const float4*)(bias + sub * 4);
        float4 o;
        o.x = (acc.x + ps * hi4.x) * inv + b4.x;
        o.y = (acc.y + ps * hi4.y) * inv + b4.y;
        o.z = (acc.z + ps * hi4.z) * inv + b4.z;
        o.w = (acc.w + ps * hi4.w) * inv + b4.w;
        *(float4*)(out + (size_t)node * FOUT + sub * 4) = o;
    }
}

// ---------------------------------------------------------------------------
extern "C" void kernel_launch(void* const* d_in, const int* in_sizes, int n_in,
                              void* d_out, int out_size) {
    const float* x       = (const float*)d_in[0];
    const int*   ei      = (const int*)d_in[1];
    const float* W       = (const float*)d_in[2];
    const float* att_src = (const float*)d_in[3];
    const float* att_dst = (const float*)d_in[4];
    const float* bias    = (const float*)d_in[5];
    float* out = (float*)d_out;

    const int n = in_sizes[0] / FIN;   // 100000
    const int e = in_sizes[1] / 2;     // 3200000
    const int nb = (n + 255) / 256;    // scan blocks (391 <= 512)

    // K1: projection + attention halves + cnt init
    k_gemm<<<(n + 127) / 128, 256>>>(x, W, att_src, att_dst, n);
    // K2: in-degree histogram
    k_hist<<<(e + 255) / 256, 256>>>(ei, e);
    // K3: exclusive scan cnt -> offs
    k_scan1<<<nb, 256>>>(n);
    k_scan2<<<1, 512>>>(nb);
    k_scan3<<<nb, 256>>>(n);
    // K4: dst-sorted scatter of src ids
    k_scatter<<<(e + 255) / 256, 256>>>(ei, e);
    // K5: warp-per-dst aggregation (+softmax normalize, self-loop, bias)
    k_agg<<<(n + 7) / 8, 256>>>(bias, out, n);
}

// round 9
// speedup vs baseline: 1.6346x; 1.0176x over previous
#include <cuda_runtime.h>
#include <cuda_bf16.h>

#define MAXN 100000
#define MAXE 3200000
#define FIN  256
#define FOUT 64

// Scratch (device globals — allocation is forbidden)
__device__ float g_h[MAXN * FOUT];     // projected features (25.6 MB, L2-resident)
__device__ float g_as[MAXN];           // h · att_src
__device__ float g_ad[MAXN];           // h · att_dst
__device__ int   g_cnt[MAXN];          // in-degree (real edges)
__device__ int   g_offs[MAXN];         // CSR offsets (exclusive scan of cnt)
__device__ int   g_bsum[512];          // scan block sums
__device__ int   g_src[MAXE];          // dst-sorted source ids
__device__ float g_p[MAXE];            // dst-sorted unnormalized softmax weights

static __device__ __forceinline__ float leaky(float v) {
    return v > 0.0f ? v : 0.2f * v;
}

// ---------------------------------------------------------------------------
// K0: zero in-degree counters (must precede gemm's fused histogram)
// ---------------------------------------------------------------------------
__global__ __launch_bounds__(256) void k_zero(int n) {
    int i = blockIdx.x * 256 + threadIdx.x;
    if (i < n) g_cnt[i] = 0;
}

// ---------------------------------------------------------------------------
// K1: h = x @ W  (scalar SGEMM, BM=128, BN=64, BK=16, 8x4/thread)
//     Double-buffered smem, register prefetch, one sync per k-tile.
//     Fused: in-degree histogram (fire-and-forget REDs at block start),
//     epilogue a_src/a_dst per row.
// ---------------------------------------------------------------------------
__global__ __launch_bounds__(256) void k_gemm(const float* __restrict__ x,
                                              const float* __restrict__ W,
                                              const float* __restrict__ att_src,
                                              const float* __restrict__ att_dst,
                                              const int* __restrict__ ei,
                                              int n, int e) {
    __shared__ float  As[2][128][17];
    __shared__ float4 Bs[2][16][16];

    const int tid  = threadIdx.x;
    const int row0 = blockIdx.x * 128;
    const int tcol = tid & 15;
    const int trow = tid >> 4;

    // ---- fused histogram: this block's slice of dst ids (REDs drain async)
    {
        int epb = (e + gridDim.x - 1) / gridDim.x;
        int e0 = blockIdx.x * epb;
        int e1 = min(e0 + epb, e);
        for (int i = e0 + tid; i < e1; i += 256)
            atomicAdd(&g_cnt[__ldg(ei + (size_t)e + i)], 1);
    }

    float acc[8][4];
#pragma unroll
    for (int i = 0; i < 8; i++)
#pragma unroll
        for (int j = 0; j < 4; j++) acc[i][j] = 0.0f;

    // ---- prologue: load k-tile 0 into buffer 0
    {
#pragma unroll
        for (int l = 0; l < 2; l++) {
            int idx = tid + l * 256;
            int r = idx >> 2, q = idx & 3;
            float4 v = make_float4(0.f, 0.f, 0.f, 0.f);
            int gr = row0 + r;
            if (gr < n)
                v = *(const float4*)(x + (size_t)gr * FIN + q * 4);
            As[0][r][q * 4 + 0] = v.x; As[0][r][q * 4 + 1] = v.y;
            As[0][r][q * 4 + 2] = v.z; As[0][r][q * 4 + 3] = v.w;
        }
        int k = tid >> 4, cq = tid & 15;
        Bs[0][k][cq] = *(const float4*)(W + (size_t)k * FOUT + cq * 4);
    }
    __syncthreads();

    int buf = 0;
    for (int k0 = 0; k0 < FIN; k0 += 16) {
        const bool has_next = (k0 + 16) < FIN;
        float4 pa0, pa1, pbv;
        if (has_next) {
            const int k1 = k0 + 16;
            {
                int r = tid >> 2, q = tid & 3;
                int gr = row0 + r;
                pa0 = (gr < n) ? *(const float4*)(x + (size_t)gr * FIN + k1 + q * 4)
                               : make_float4(0.f, 0.f, 0.f, 0.f);
            }
            {
                int idx = tid + 256;
                int r = idx >> 2, q = idx & 3;
                int gr = row0 + r;
                pa1 = (gr < n) ? *(const float4*)(x + (size_t)gr * FIN + k1 + q * 4)
                               : make_float4(0.f, 0.f, 0.f, 0.f);
            }
            {
                int k = tid >> 4, cq = tid & 15;
                pbv = *(const float4*)(W + (size_t)(k1 + k) * FOUT + cq * 4);
            }
        }

#pragma unroll
        for (int kk = 0; kk < 16; kk++) {
            float4 b = Bs[buf][kk][tcol];
#pragma unroll
            for (int i = 0; i < 8; i++) {
                float a = As[buf][trow + 16 * i][kk];
                acc[i][0] += a * b.x;
                acc[i][1] += a * b.y;
                acc[i][2] += a * b.z;
                acc[i][3] += a * b.w;
            }
        }

        if (has_next) {
            int nb = buf ^ 1;
            {
                int r = tid >> 2, q = tid & 3;
                As[nb][r][q * 4 + 0] = pa0.x; As[nb][r][q * 4 + 1] = pa0.y;
                As[nb][r][q * 4 + 2] = pa0.z; As[nb][r][q * 4 + 3] = pa0.w;
            }
            {
                int idx = tid + 256;
                int r = idx >> 2, q = idx & 3;
                As[nb][r][q * 4 + 0] = pa1.x; As[nb][r][q * 4 + 1] = pa1.y;
                As[nb][r][q * 4 + 2] = pa1.z; As[nb][r][q * 4 + 3] = pa1.w;
            }
            {
                int k = tid >> 4, cq = tid & 15;
                Bs[nb][k][cq] = pbv;
            }
            __syncthreads();
            buf = nb;
        }
    }

    const float4 asv = *(const float4*)(att_src + tcol * 4);
    const float4 adv = *(const float4*)(att_dst + tcol * 4);

#pragma unroll
    for (int i = 0; i < 8; i++) {
        int r = row0 + trow + 16 * i;
        float sa = acc[i][0] * asv.x + acc[i][1] * asv.y
                 + acc[i][2] * asv.z + acc[i][3] * asv.w;
        float sd = acc[i][0] * adv.x + acc[i][1] * adv.y
                 + acc[i][2] * adv.z + acc[i][3] * adv.w;
#pragma unroll
        for (int o = 8; o > 0; o >>= 1) {
            sa += __shfl_xor_sync(0xFFFFFFFFu, sa, o);
            sd += __shfl_xor_sync(0xFFFFFFFFu, sd, o);
        }
        if (r < n) {
            *(float4*)(g_h + (size_t)r * FOUT + tcol * 4) =
                make_float4(acc[i][0], acc[i][1], acc[i][2], acc[i][3]);
            if (tcol == 0) {
                g_as[r] = sa;
                g_ad[r] = sd;
            }
        }
    }
}

// ---------------------------------------------------------------------------
// K2a/b/c: exclusive prefix scan over cnt -> offs
// ---------------------------------------------------------------------------
__global__ __launch_bounds__(256) void k_scan1(int n) {
    __shared__ int sh[256];
    int i = blockIdx.x * 256 + threadIdx.x;
    int v = (i < n) ? g_cnt[i] : 0;
    sh[threadIdx.x] = v;
    __syncthreads();
#pragma unroll
    for (int o = 1; o < 256; o <<= 1) {
        int t = (threadIdx.x >= o) ? sh[threadIdx.x - o] : 0;
        __syncthreads();
        sh[threadIdx.x] += t;
        __syncthreads();
    }
    if (i < n) g_offs[i] = sh[threadIdx.x] - v;        // exclusive
    if (threadIdx.x == 255) g_bsum[blockIdx.x] = sh[255];
}

__global__ __launch_bounds__(512) void k_scan2(int nb) {
    __shared__ int sh[512];
    int t = threadIdx.x;
    int v = (t < nb) ? g_bsum[t] : 0;
    sh[t] = v;
    __syncthreads();
#pragma unroll
    for (int o = 1; o < 512; o <<= 1) {
        int u = (t >= o) ? sh[t - o] : 0;
        __syncthreads();
        sh[t] += u;
        __syncthreads();
    }
    if (t < nb) g_bsum[t] = sh[t] - v;                  // exclusive
}

__global__ __launch_bounds__(256) void k_scan3(int n) {
    int i = blockIdx.x * 256 + threadIdx.x;
    if (i < n) g_offs[i] += g_bsum[blockIdx.x];
}

// ---------------------------------------------------------------------------
// K3: scatter — dst-sorted (src, p) pairs; p = exp(leakyrelu(as[s]+ad[d])).
//     Advances offs[d] to its end; agg recovers start = end - cnt.
// ---------------------------------------------------------------------------
__global__ __launch_bounds__(256) void k_scatter(const int* __restrict__ ei, int e) {
    int i = blockIdx.x * 256 + threadIdx.x;
    if (i >= e) return;
    int s = __ldg(ei + i);
    int d = __ldg(ei + e + i);
    float p = __expf(leaky(__ldg(&g_as[s]) + __ldg(&g_ad[d])));
    int pos = atomicAdd(&g_offs[d], 1);
    g_src[pos] = s;
    g_p[pos]   = p;
}

// ---------------------------------------------------------------------------
// K4: warp-per-dst aggregation, 4 edges in flight per warp (2 subgroups x
//     unroll 2). Epilogue: self-loop + normalize + bias; single store.
// ---------------------------------------------------------------------------
__global__ __launch_bounds__(256) void k_agg(const float* __restrict__ bias,
                                             float* __restrict__ out, int n) {
    int node = (int)((blockIdx.x * 256u + threadIdx.x) >> 5);
    if (node >= n) return;
    int lane = threadIdx.x & 31;
    int sub  = lane & 15;
    int half = lane >> 4;               // 0 or 1

    int end   = g_offs[node];           // post-scatter: end offset
    int start = end - g_cnt[node];

    float4 acc = make_float4(0.f, 0.f, 0.f, 0.f);
    float denl = 0.0f;

    int base = start;
    for (; base + 4 <= end; base += 4) {
        int i0 = base + half;
        int i1 = i0 + 2;
        int   s0 = __ldg(&g_src[i0]);
        int   s1 = __ldg(&g_src[i1]);
        float p0 = __ldg(&g_p[i0]);
        float p1 = __ldg(&g_p[i1]);
        const float4 h0 = *(const float4*)(g_h + (size_t)s0 * FOUT + sub * 4);
        const float4 h1 = *(const float4*)(g_h + (size_t)s1 * FOUT + sub * 4);
        acc.x += p0 * h0.x + p1 * h1.x;
        acc.y += p0 * h0.y + p1 * h1.y;
        acc.z += p0 * h0.z + p1 * h1.z;
        acc.w += p0 * h0.w + p1 * h1.w;
        if (sub == 0) denl += p0 + p1;
    }
    for (; base < end; base += 2) {
        int i0 = base + half;
        if (i0 < end) {
            int   s0 = __ldg(&g_src[i0]);
            float p0 = __ldg(&g_p[i0]);
            const float4 h0 = *(const float4*)(g_h + (size_t)s0 * FOUT + sub * 4);
            acc.x += p0 * h0.x;
            acc.y += p0 * h0.y;
            acc.z += p0 * h0.z;
            acc.w += p0 * h0.w;
            if (sub == 0) denl += p0;
        }
    }

    // combine the two 16-lane subgroups
    acc.x += __shfl_xor_sync(0xFFFFFFFFu, acc.x, 16);
    acc.y += __shfl_xor_sync(0xFFFFFFFFu, acc.y, 16);
    acc.z += __shfl_xor_sync(0xFFFFFFFFu, acc.z, 16);
    acc.w += __shfl_xor_sync(0xFFFFFFFFu, acc.w, 16);
    float den = __shfl_sync(0xFFFFFFFFu, denl, 0)
              + __shfl_sync(0xFFFFFFFFu, denl, 16);

    float ps  = __expf(leaky(g_as[node] + g_ad[node]));   // self-loop weight
    float inv = 1.0f / (den + ps + 1e-16f);

    if (lane < 16) {
        const float4 hi4 = *(const float4*)(g_h + (size_t)node * FOUT + sub * 4);
        const float4 b4  = *(const float4*)(bias + sub * 4);
        float4 o;
        o.x = (acc.x + ps * hi4.x) * inv + b4.x;
        o.y = (acc.y + ps * hi4.y) * inv + b4.y;
        o.z = (acc.z + ps * hi4.z) * inv + b4.z;
        o.w = (acc.w + ps * hi4.w) * inv + b4.w;
        *(float4*)(out + (size_t)node * FOUT + sub * 4) = o;
    }
}

// ---------------------------------------------------------------------------
extern "C" void kernel_launch(void* const* d_in, const int* in_sizes, int n_in,
                              void* d_out, int out_size) {
    const float* x       = (const float*)d_in[0];
    const int*   ei      = (const int*)d_in[1];
    const float* W       = (const float*)d_in[2];
    const float* att_src = (const float*)d_in[3];
    const float* att_dst = (const float*)d_in[4];
    const float* bias    = (const float*)d_in[5];
    float* out = (float*)d_out;

    const int n = in_sizes[0] / FIN;   // 100000
    const int e = in_sizes[1] / 2;     // 3200000
    const int nb = (n + 255) / 256;    // scan blocks (391 <= 512)

    // K0: zero counters (before gemm's fused histogram)
    k_zero<<<nb, 256>>>(n);
    // K1: projection + attention halves + fused in-degree histogram
    k_gemm<<<(n + 127) / 128, 256>>>(x, W, att_src, att_dst, ei, n, e);
    // K2: exclusive scan cnt -> offs
    k_scan1<<<nb, 256>>>(n);
    k_scan2<<<1, 512>>>(nb);
    k_scan3<<<nb, 256>>>(n);
    // K3: dst-sorted scatter of (src, p)
    k_scatter<<<(e + 255) / 256, 256>>>(ei, e);
    // K4: warp-per-dst aggregation (+softmax normalize, self-loop, bias)
    k_agg<<<(n + 7) / 8, 256>>>(bias, out, n);
}